// round 4
// baseline (speedup 1.0000x reference)
#include <cuda_runtime.h>

#define LL    128
#define NANG  120
#define TB    128
#define TX    16
#define TY    16
#define ZC    16
#define ROWS  32
#define RS    20
#define NBUF  3

// ---- packed f32x2 helpers ----
__device__ __forceinline__ unsigned long long pack2(float x, float y) {
    unsigned long long r;
    asm("mov.b64 %0, {%1, %2};" : "=l"(r) : "f"(x), "f"(y));
    return r;
}
__device__ __forceinline__ void ffma2(unsigned long long &acc, unsigned long long v,
                                      unsigned long long w) {
    asm("fma.rn.f32x2 %0, %1, %2, %0;" : "+l"(acc) : "l"(v), "l"(w));
}
__device__ __forceinline__ void unpack2(unsigned long long v, float &x, float &y) {
    asm("mov.b64 {%0, %1}, %2;" : "=f"(x), "=f"(y) : "l"(v));
}
__device__ __forceinline__ void lds2(unsigned long long &a, unsigned long long &b,
                                     unsigned addr) {
    asm volatile("ld.shared.v2.u64 {%0, %1}, [%2];" : "=l"(a), "=l"(b) : "r"(addr));
}

// 4 independent global loads for this thread's staging slice (MLP=4)
__device__ __forceinline__ void ldg4(float r[4], const float * __restrict__ img_a,
                                     int ymin, int rbase, int z) {
    #pragma unroll
    for (int k = 0; k < 4; ++k) {
        int gy = min(max(ymin + rbase + 8 * k, 0), LL - 1);
        r[k] = __ldg(img_a + gy * LL + z);
    }
}
__device__ __forceinline__ void sts4(float *dst, const float r[4], int rbase, int z) {
    #pragma unroll
    for (int k = 0; k < 4; ++k) dst[(rbase + 8 * k) * RS + z] = r[k];
}

__global__ __launch_bounds__(TB, 7)
void bp_kernel(const float * __restrict__ image, const float * __restrict__ angles,
               float * __restrict__ out) {
    __shared__ float2 s_tab[NANG];
    __shared__ __align__(16) float s_img[NBUF][ROWS * RS];

    const int tid = threadIdx.x;
    if (tid < NANG) {
        float ph = -angles[tid] * 0.017453292519943295f;
        float sv, cv;
        sincosf(ph, &sv, &cv);
        s_tab[tid] = make_float2(cv, sv);
    }

    const int tileX0 = (blockIdx.x & 7) * TX;
    const int tileY0 = (blockIdx.x >> 3) * TY;
    const int z0 = blockIdx.y * ZC;
    const int b  = blockIdx.z;

    const int warp = tid >> 5, lane = tid & 31;
    const int px = tileX0 + (warp & 1) * 8 + (lane & 7);
    const int pr = (warp >> 1) * 4 + (lane >> 3);
    const int py = tileY0 + 2 * pr;
    const float Xp = px - 63.5f, Yp = py - 63.5f;
    const float X0f = tileX0 - 63.5f, X1f = X0f + (TX - 1);
    const float Y0f = tileY0 - 63.5f, Y1f = Y0f + (TY - 1);

    const float *img_b = image + (size_t)b * NANG * LL * LL + z0;
    const int zst = tid & 15, rbase = tid >> 4;

    unsigned long long acc[16];
    #pragma unroll
    for (int i = 0; i < 16; ++i) acc[i] = 0ULL;
    float n1 = 0.0f, n2 = 0.0f;

    __syncthreads();  // s_tab ready

    const unsigned sm0 = (unsigned)__cvta_generic_to_shared(&s_img[0][0]);

    auto yminf = [&](int a) -> int {
        float2 cs = s_tab[a];
        float m = fminf(-cs.y * X0f, -cs.y * X1f) + fminf(cs.x * Y0f, cs.x * Y1f) + 63.5f;
        return (int)floorf(m) - 1;
    };

    // prologue: angle 0 fully staged into buf0; angle 1 LDG'd into hold regs
    int y_c = yminf(0);
    {
        float tmp[4];
        ldg4(tmp, img_b, y_c, rbase, zst);
        sts4(&s_img[0][0], tmp, rbase, zst);
    }
    int y_n = yminf(1);
    float hold[4];
    ldg4(hold, img_b + (size_t)LL * LL, y_n, rbase, zst);
    int y_n2 = y_n;

    int bufc = 0;
    for (int a = 0; a < NANG; ++a) {
        int bw = bufc + 1; if (bw == NBUF) bw = 0;
        if (a + 1 < NANG) sts4(&s_img[bw][0], hold, rbase, zst);
        __syncthreads();   // drains STS: buf[bufc] complete; protects buf[bw] anti-dep
        if (a + 2 < NANG) {
            y_n2 = yminf(a + 2);
            ldg4(hold, img_b + (size_t)(a + 2) * LL * LL, y_n2, rbase, zst);
        }

        const float2 cs = s_tab[a];
        const float c = cs.x, s = cs.y;

        float sx = fmaf(c, Xp, fmaf(s, Yp, 63.5f));
        float sy = fmaf(c, Yp, fmaf(-s, Xp, 63.5f));
        float sx2 = sx + s;
        float sy2 = sy + c;
        float y0f = floorf(sy), y2f = floorf(sy2);
        float wx  = sx  - floorf(sx);
        float wy  = sy  - y0f;
        float wx2 = sx2 - floorf(sx2);
        float wy2 = sy2 - y2f;

        // float-domain bounds: x0 valid <=> sx in [0,128); x0+1 valid <=> sx in [-1,127)
        float hx = 0.0f;
        if (sx >= 0.0f  && sx < 128.0f) hx = 1.0f - wx;
        if (sx >= -1.0f && sx < 127.0f) hx += wx;
        float A0 = (sy >= 0.0f  && sy < 128.0f) ? hx * (1.0f - wy) : 0.0f;
        float A1 = (sy >= -1.0f && sy < 127.0f) ? hx * wy          : 0.0f;

        float hx2 = 0.0f;
        if (sx2 >= 0.0f  && sx2 < 128.0f) hx2 = 1.0f - wx2;
        if (sx2 >= -1.0f && sx2 < 127.0f) hx2 += wx2;
        float B0 = (sy2 >= 0.0f  && sy2 < 128.0f) ? hx2 * (1.0f - wy2) : 0.0f;
        float B1 = (sy2 >= -1.0f && sy2 < 127.0f) ? hx2 * wy2          : 0.0f;

        n1 += A0 + A1;
        n2 += B0 + B1;

        bool dneg = (y2f < y0f), dpos = (y2f > y0f), dd = (y2f != y0f);
        int r0 = (int)fminf(y0f, y2f) - y_c;   // analytically in [0, ROWS-3]

        unsigned long long Wa0 = pack2(dneg ? 0.0f : A0, dneg ? 0.0f : A0);
        unsigned long long Wa1 = pack2(dneg ? A0 : A1,   dneg ? A0 : A1);
        unsigned long long Wa2 = pack2(dneg ? A1 : 0.0f, dneg ? A1 : 0.0f);
        unsigned long long Wb0 = pack2(dpos ? 0.0f : B0, dpos ? 0.0f : B0);
        unsigned long long Wb1 = pack2(dpos ? B0 : B1,   dpos ? B0 : B1);
        unsigned long long Wb2 = pack2(dpos ? B1 : 0.0f, dpos ? B1 : 0.0f);

        unsigned a0addr = sm0 + (unsigned)(bufc * (ROWS * RS * 4)) + (unsigned)r0 * (RS * 4);

        #pragma unroll
        for (int q = 0; q < 4; ++q) {
            unsigned long long p00, p01, p10, p11;
            unsigned long long p20 = 0ULL, p21 = 0ULL;
            lds2(p00, p01, a0addr + q * 16);
            lds2(p10, p11, a0addr + RS * 4 + q * 16);
            if (dd) lds2(p20, p21, a0addr + 2 * RS * 4 + q * 16);
            ffma2(acc[2 * q],     p00, Wa0);
            ffma2(acc[2 * q + 1], p01, Wa0);
            ffma2(acc[2 * q],     p10, Wa1);
            ffma2(acc[2 * q + 1], p11, Wa1);
            ffma2(acc[2 * q],     p20, Wa2);
            ffma2(acc[2 * q + 1], p21, Wa2);
            ffma2(acc[8 + 2 * q],     p00, Wb0);
            ffma2(acc[8 + 2 * q + 1], p01, Wb0);
            ffma2(acc[8 + 2 * q],     p10, Wb1);
            ffma2(acc[8 + 2 * q + 1], p11, Wb1);
            ffma2(acc[8 + 2 * q],     p20, Wb2);
            ffma2(acc[8 + 2 * q + 1], p21, Wb2);
        }

        y_c = y_n; y_n = y_n2;
        bufc = bw;
    }

    // epilogue
    float inv1 = 1.0f / (n1 + 1e-11f);
    float inv2 = 1.0f / (n2 + 1e-11f);
    float *op = out + (((size_t)b * LL + px) * LL + py) * LL + z0;
    #pragma unroll
    for (int q = 0; q < 4; ++q) {
        float ax, ay, bx, by;
        unpack2(acc[2 * q],     ax, ay);
        unpack2(acc[2 * q + 1], bx, by);
        *reinterpret_cast<float4 *>(op + q * 4) =
            make_float4(ax * inv1, ay * inv1, bx * inv1, by * inv1);
    }
    float *op2 = op + LL;
    #pragma unroll
    for (int q = 0; q < 4; ++q) {
        float ax, ay, bx, by;
        unpack2(acc[8 + 2 * q],     ax, ay);
        unpack2(acc[8 + 2 * q + 1], bx, by);
        *reinterpret_cast<float4 *>(op2 + q * 4) =
            make_float4(ax * inv2, ay * inv2, bx * inv2, by * inv2);
    }
}

extern "C" void kernel_launch(void *const *d_in, const int *in_sizes, int n_in,
                              void *d_out, int out_size) {
    const float *image  = (const float *)d_in[0];
    const float *angles = (const float *)d_in[1];
    float *out = (float *)d_out;
    dim3 grid(64, LL / ZC /*8*/, 2 /*B*/);
    bp_kernel<<<grid, TB>>>(image, angles, out);
}

// round 5
// speedup vs baseline: 1.0878x; 1.0878x over previous
#include <cuda_runtime.h>

#define LL    128
#define NANG  120
#define TB    64      // 2 warps per CTA
#define TX    8       // CTA px extent
#define TY    16      // CTA py extent (8 pairs)
#define ZC    32      // z per thread (per pixel)
#define ROWS  24      // staged rows per angle (need <=21 for 8x16 tile)
#define RS    36      // smem row stride in floats
#define NST   12      // staging loads per thread (ROWS*ZC/TB)

// ---- packed f32x2 helpers ----
__device__ __forceinline__ unsigned long long pack2(float x, float y) {
    unsigned long long r;
    asm("mov.b64 %0, {%1, %2};" : "=l"(r) : "f"(x), "f"(y));
    return r;
}
__device__ __forceinline__ void ffma2(unsigned long long &acc, unsigned long long v,
                                      unsigned long long w) {
    asm("fma.rn.f32x2 %0, %1, %2, %0;" : "+l"(acc) : "l"(v), "l"(w));
}
__device__ __forceinline__ void unpack2(unsigned long long v, float &x, float &y) {
    asm("mov.b64 {%0, %1}, %2;" : "=f"(x), "=f"(y) : "l"(v));
}
__device__ __forceinline__ void lds2(unsigned long long &a, unsigned long long &b,
                                     unsigned addr) {
    asm volatile("ld.shared.v2.u64 {%0, %1}, [%2];" : "=l"(a), "=l"(b) : "r"(addr));
}

__device__ __forceinline__ void ldg12(float r[NST], const float * __restrict__ img_a,
                                      int ymin, int rbase, int z) {
    #pragma unroll
    for (int k = 0; k < NST; ++k) {
        int gy = min(max(ymin + rbase + 2 * k, 0), LL - 1);
        r[k] = __ldg(img_a + gy * LL + z);
    }
}
__device__ __forceinline__ void sts12(float *dst, const float r[NST], int rbase, int z) {
    #pragma unroll
    for (int k = 0; k < NST; ++k) dst[(rbase + 2 * k) * RS + z] = r[k];
}

__global__ __launch_bounds__(TB, 7)
void bp_kernel(const float * __restrict__ image, const float * __restrict__ angles,
               float * __restrict__ out) {
    __shared__ float2 s_tab[NANG];
    __shared__ __align__(16) float s_img[2][ROWS * RS];

    const int tid = threadIdx.x;
    for (int t = tid; t < NANG; t += TB) {
        float ph = -angles[t] * 0.017453292519943295f;
        float sv, cv;
        sincosf(ph, &sv, &cv);
        s_tab[t] = make_float2(cv, sv);
    }

    const int tileX0 = (blockIdx.x & 15) * TX;
    const int tileY0 = (blockIdx.x >> 4) * TY;
    const int z0 = blockIdx.y * ZC;
    const int b  = blockIdx.z;

    const int warp = tid >> 5, lane = tid & 31;
    const int px = tileX0 + (lane & 7);
    const int pr = warp * 4 + (lane >> 3);          // pair index 0..7
    const int py = tileY0 + 2 * pr;
    const float Xp = px - 63.5f, Yp = py - 63.5f;
    const float X0f = tileX0 - 63.5f, X1f = X0f + (TX - 1);
    const float Y0f = tileY0 - 63.5f, Y1f = Y0f + (TY - 1);

    const float *img_b = image + (size_t)b * NANG * LL * LL + z0;
    const int zst = lane;            // staging z lane (0..31)
    const int rbase = warp;          // staging row base (0..1)

    unsigned long long acc[32];      // [0..15]=pixel1 (32 z), [16..31]=pixel2
    #pragma unroll
    for (int i = 0; i < 32; ++i) acc[i] = 0ULL;
    float n1 = 0.0f, n2 = 0.0f;

    __syncthreads();  // s_tab ready

    const unsigned sm0 = (unsigned)__cvta_generic_to_shared(&s_img[0][0]);

    auto yminf = [&](int a) -> int {
        float2 cs = s_tab[a];
        float m = fminf(-cs.y * X0f, -cs.y * X1f) + fminf(cs.x * Y0f, cs.x * Y1f) + 63.5f;
        return (int)floorf(m) - 1;
    };

    // prologue: angle 0 staged into buf0; angle 1 LDG'd into hold
    int y_c = yminf(0);
    {
        float t[NST];
        ldg12(t, img_b, y_c, rbase, zst);
        sts12(&s_img[0][0], t, rbase, zst);
    }
    int y_n = yminf(1);
    float hold[NST];
    ldg12(hold, img_b + (size_t)LL * LL, y_n, rbase, zst);
    int y_n2 = y_n;

    for (int a = 0; a < NANG; ++a) {
        __syncthreads();   // buf[a&1] staged & visible; readers of buf[(a+1)&1] done

        const float2 cs = s_tab[a];
        const float c = cs.x, s = cs.y;

        float sx = fmaf(c, Xp, fmaf(s, Yp, 63.5f));
        float sy = fmaf(c, Yp, fmaf(-s, Xp, 63.5f));
        float sx2 = sx + s;
        float sy2 = sy + c;
        float y0f = floorf(sy), y2f = floorf(sy2);
        float wx  = sx  - floorf(sx);
        float wy  = sy  - y0f;
        float wx2 = sx2 - floorf(sx2);
        float wy2 = sy2 - y2f;

        float hx = 0.0f;
        if (sx >= 0.0f  && sx < 128.0f) hx = 1.0f - wx;
        if (sx >= -1.0f && sx < 127.0f) hx += wx;
        float A0 = (sy >= 0.0f  && sy < 128.0f) ? hx * (1.0f - wy) : 0.0f;
        float A1 = (sy >= -1.0f && sy < 127.0f) ? hx * wy          : 0.0f;

        float hx2 = 0.0f;
        if (sx2 >= 0.0f  && sx2 < 128.0f) hx2 = 1.0f - wx2;
        if (sx2 >= -1.0f && sx2 < 127.0f) hx2 += wx2;
        float B0 = (sy2 >= 0.0f  && sy2 < 128.0f) ? hx2 * (1.0f - wy2) : 0.0f;
        float B1 = (sy2 >= -1.0f && sy2 < 127.0f) ? hx2 * wy2          : 0.0f;

        n1 += A0 + A1;
        n2 += B0 + B1;

        bool dneg = (y2f < y0f), dpos = (y2f > y0f), dd = (y2f != y0f);
        int r0 = (int)fminf(y0f, y2f) - y_c;   // analytically in [0, ROWS-3]

        unsigned long long Wa0 = pack2(dneg ? 0.0f : A0, dneg ? 0.0f : A0);
        unsigned long long Wa1 = pack2(dneg ? A0 : A1,   dneg ? A0 : A1);
        unsigned long long Wa2 = pack2(dneg ? A1 : 0.0f, dneg ? A1 : 0.0f);
        unsigned long long Wb0 = pack2(dpos ? 0.0f : B0, dpos ? 0.0f : B0);
        unsigned long long Wb1 = pack2(dpos ? B0 : B1,   dpos ? B0 : B1);
        unsigned long long Wb2 = pack2(dpos ? B1 : 0.0f, dpos ? B1 : 0.0f);

        unsigned a0addr = sm0 + (unsigned)((a & 1) * (ROWS * RS * 4))
                              + (unsigned)r0 * (RS * 4);

        #pragma unroll
        for (int q = 0; q < 8; ++q) {
            unsigned long long p00, p01, p10, p11;
            unsigned long long p20 = 0ULL, p21 = 0ULL;
            lds2(p00, p01, a0addr + q * 16);
            lds2(p10, p11, a0addr + RS * 4 + q * 16);
            if (dd) lds2(p20, p21, a0addr + 2 * RS * 4 + q * 16);
            ffma2(acc[2 * q],     p00, Wa0);
            ffma2(acc[2 * q + 1], p01, Wa0);
            ffma2(acc[2 * q],     p10, Wa1);
            ffma2(acc[2 * q + 1], p11, Wa1);
            ffma2(acc[2 * q],     p20, Wa2);
            ffma2(acc[2 * q + 1], p21, Wa2);
            ffma2(acc[16 + 2 * q],     p00, Wb0);
            ffma2(acc[16 + 2 * q + 1], p01, Wb0);
            ffma2(acc[16 + 2 * q],     p10, Wb1);
            ffma2(acc[16 + 2 * q + 1], p11, Wb1);
            ffma2(acc[16 + 2 * q],     p20, Wb2);
            ffma2(acc[16 + 2 * q + 1], p21, Wb2);
        }

        // stage next: STS(a+1) from hold (LDG'd one full iteration ago),
        // then issue LDG(a+2) -> has the whole next compute body to land
        if (a + 1 < NANG) sts12(&s_img[(a + 1) & 1][0], hold, rbase, zst);
        if (a + 2 < NANG) {
            y_n2 = yminf(a + 2);
            ldg12(hold, img_b + (size_t)(a + 2) * LL * LL, y_n2, rbase, zst);
        }
        y_c = y_n; y_n = y_n2;
    }

    // epilogue
    float inv1 = 1.0f / (n1 + 1e-11f);
    float inv2 = 1.0f / (n2 + 1e-11f);
    float *op = out + (((size_t)b * LL + px) * LL + py) * LL + z0;
    #pragma unroll
    for (int q = 0; q < 8; ++q) {
        float ax, ay, bx, by;
        unpack2(acc[2 * q],     ax, ay);
        unpack2(acc[2 * q + 1], bx, by);
        *reinterpret_cast<float4 *>(op + q * 4) =
            make_float4(ax * inv1, ay * inv1, bx * inv1, by * inv1);
    }
    float *op2 = op + LL;
    #pragma unroll
    for (int q = 0; q < 8; ++q) {
        float ax, ay, bx, by;
        unpack2(acc[16 + 2 * q],     ax, ay);
        unpack2(acc[16 + 2 * q + 1], bx, by);
        *reinterpret_cast<float4 *>(op2 + q * 4) =
            make_float4(ax * inv2, ay * inv2, bx * inv2, by * inv2);
    }
}

extern "C" void kernel_launch(void *const *d_in, const int *in_sizes, int n_in,
                              void *d_out, int out_size) {
    const float *image  = (const float *)d_in[0];
    const float *angles = (const float *)d_in[1];
    float *out = (float *)d_out;
    dim3 grid(128 /* 16 x-tiles * 8 y-tiles */, LL / ZC /*4*/, 2 /*B*/);
    bp_kernel<<<grid, TB>>>(image, angles, out);
}

// round 6
// speedup vs baseline: 1.0886x; 1.0007x over previous
#include <cuda_runtime.h>

#define LL    128
#define NANG  120
#define TB    64      // 2 warps per CTA
#define TX    8       // CTA px extent
#define TY    16      // CTA py extent (8 pairs)
#define ZC    32      // z per thread (per pixel)
#define ROWS  24      // staged rows per angle (need <=21 for 8x16 tile)
#define RS    36      // smem row stride in floats
#define NST   12      // staging loads per thread (ROWS*ZC/TB)

// ---- packed f32x2 helpers ----
__device__ __forceinline__ unsigned long long pack2(float x, float y) {
    unsigned long long r;
    asm("mov.b64 %0, {%1, %2};" : "=l"(r) : "f"(x), "f"(y));
    return r;
}
__device__ __forceinline__ void ffma2(unsigned long long &acc, unsigned long long v,
                                      unsigned long long w) {
    asm("fma.rn.f32x2 %0, %1, %2, %0;" : "+l"(acc) : "l"(v), "l"(w));
}
__device__ __forceinline__ void unpack2(unsigned long long v, float &x, float &y) {
    asm("mov.b64 {%0, %1}, %2;" : "=f"(x), "=f"(y) : "l"(v));
}
__device__ __forceinline__ void lds2(unsigned long long &a, unsigned long long &b,
                                     unsigned addr) {
    asm volatile("ld.shared.v2.u64 {%0, %1}, [%2];" : "=l"(a), "=l"(b) : "r"(addr));
}

__device__ __forceinline__ void ldg12(float r[NST], const float * __restrict__ img_a,
                                      int ymin, int rbase, int z) {
    #pragma unroll
    for (int k = 0; k < NST; ++k) {
        int gy = min(max(ymin + rbase + 2 * k, 0), LL - 1);
        r[k] = __ldg(img_a + gy * LL + z);
    }
}
__device__ __forceinline__ void sts12(float *dst, const float r[NST], int rbase, int z) {
    #pragma unroll
    for (int k = 0; k < NST; ++k) dst[(rbase + 2 * k) * RS + z] = r[k];
}

__global__ __launch_bounds__(TB, 7)
void bp_kernel(const float * __restrict__ image, const float * __restrict__ angles,
               float * __restrict__ out) {
    __shared__ float2 s_tab[NANG];
    __shared__ __align__(16) float s_img[2][ROWS * RS];

    const int tid = threadIdx.x;
    for (int t = tid; t < NANG; t += TB) {
        float ph = -angles[t] * 0.017453292519943295f;
        float sv, cv;
        sincosf(ph, &sv, &cv);
        s_tab[t] = make_float2(cv, sv);
    }

    const int tileX0 = (blockIdx.x & 15) * TX;
    const int tileY0 = (blockIdx.x >> 4) * TY;
    const int z0 = blockIdx.y * ZC;
    const int b  = blockIdx.z;

    const int warp = tid >> 5, lane = tid & 31;
    const int px = tileX0 + (lane & 7);
    const int pr = warp * 4 + (lane >> 3);          // pair index 0..7
    const int py = tileY0 + 2 * pr;
    const float Xp = px - 63.5f, Yp = py - 63.5f;
    const float X0f = tileX0 - 63.5f, X1f = X0f + (TX - 1);
    const float Y0f = tileY0 - 63.5f, Y1f = Y0f + (TY - 1);

    const float *img_b = image + (size_t)b * NANG * LL * LL + z0;
    const int zst = lane;            // staging z lane (0..31)
    const int rbase = warp;          // staging row base (0..1)

    unsigned long long acc[32];      // [0..15]=pixel1 (32 z), [16..31]=pixel2
    #pragma unroll
    for (int i = 0; i < 32; ++i) acc[i] = 0ULL;
    float n1 = 0.0f, n2 = 0.0f;

    __syncthreads();  // s_tab ready

    const unsigned sm0 = (unsigned)__cvta_generic_to_shared(&s_img[0][0]);

    auto yminf = [&](int a) -> int {
        float2 cs = s_tab[a];
        float m = fminf(-cs.y * X0f, -cs.y * X1f) + fminf(cs.x * Y0f, cs.x * Y1f) + 63.5f;
        return (int)floorf(m) - 1;
    };

    // prologue: angle 0 staged into buf0; angle 1 LDG'd into hold
    int y_c = yminf(0);
    {
        float t[NST];
        ldg12(t, img_b, y_c, rbase, zst);
        sts12(&s_img[0][0], t, rbase, zst);
    }
    int y_n = yminf(1);
    float hold[NST];
    ldg12(hold, img_b + (size_t)LL * LL, y_n, rbase, zst);
    int y_n2 = y_n;

    for (int a = 0; a < NANG; ++a) {
        __syncthreads();   // buf[a&1] staged & visible; readers of buf[(a+1)&1] done

        const float2 cs = s_tab[a];
        const float c = cs.x, s = cs.y;

        float sx = fmaf(c, Xp, fmaf(s, Yp, 63.5f));
        float sy = fmaf(c, Yp, fmaf(-s, Xp, 63.5f));
        float sx2 = sx + s;
        float sy2 = sy + c;
        float y0f = floorf(sy), y2f = floorf(sy2);
        float wx  = sx  - floorf(sx);
        float wy  = sy  - y0f;
        float wx2 = sx2 - floorf(sx2);
        float wy2 = sy2 - y2f;

        float hx = 0.0f;
        if (sx >= 0.0f  && sx < 128.0f) hx = 1.0f - wx;
        if (sx >= -1.0f && sx < 127.0f) hx += wx;
        float A0 = (sy >= 0.0f  && sy < 128.0f) ? hx * (1.0f - wy) : 0.0f;
        float A1 = (sy >= -1.0f && sy < 127.0f) ? hx * wy          : 0.0f;

        float hx2 = 0.0f;
        if (sx2 >= 0.0f  && sx2 < 128.0f) hx2 = 1.0f - wx2;
        if (sx2 >= -1.0f && sx2 < 127.0f) hx2 += wx2;
        float B0 = (sy2 >= 0.0f  && sy2 < 128.0f) ? hx2 * (1.0f - wy2) : 0.0f;
        float B1 = (sy2 >= -1.0f && sy2 < 127.0f) ? hx2 * wy2          : 0.0f;

        n1 += A0 + A1;
        n2 += B0 + B1;

        bool dneg = (y2f < y0f), dpos = (y2f > y0f), dd = (y2f != y0f);
        int r0 = (int)fminf(y0f, y2f) - y_c;   // analytically in [0, ROWS-3]

        unsigned long long Wa0 = pack2(dneg ? 0.0f : A0, dneg ? 0.0f : A0);
        unsigned long long Wa1 = pack2(dneg ? A0 : A1,   dneg ? A0 : A1);
        unsigned long long Wa2 = pack2(dneg ? A1 : 0.0f, dneg ? A1 : 0.0f);
        unsigned long long Wb0 = pack2(dpos ? 0.0f : B0, dpos ? 0.0f : B0);
        unsigned long long Wb1 = pack2(dpos ? B0 : B1,   dpos ? B0 : B1);
        unsigned long long Wb2 = pack2(dpos ? B1 : 0.0f, dpos ? B1 : 0.0f);

        unsigned a0addr = sm0 + (unsigned)((a & 1) * (ROWS * RS * 4))
                              + (unsigned)r0 * (RS * 4);

        #pragma unroll
        for (int q = 0; q < 8; ++q) {
            unsigned long long p00, p01, p10, p11;
            unsigned long long p20 = 0ULL, p21 = 0ULL;
            lds2(p00, p01, a0addr + q * 16);
            lds2(p10, p11, a0addr + RS * 4 + q * 16);
            if (dd) lds2(p20, p21, a0addr + 2 * RS * 4 + q * 16);
            ffma2(acc[2 * q],     p00, Wa0);
            ffma2(acc[2 * q + 1], p01, Wa0);
            ffma2(acc[2 * q],     p10, Wa1);
            ffma2(acc[2 * q + 1], p11, Wa1);
            ffma2(acc[2 * q],     p20, Wa2);
            ffma2(acc[2 * q + 1], p21, Wa2);
            ffma2(acc[16 + 2 * q],     p00, Wb0);
            ffma2(acc[16 + 2 * q + 1], p01, Wb0);
            ffma2(acc[16 + 2 * q],     p10, Wb1);
            ffma2(acc[16 + 2 * q + 1], p11, Wb1);
            ffma2(acc[16 + 2 * q],     p20, Wb2);
            ffma2(acc[16 + 2 * q + 1], p21, Wb2);
        }

        // stage next: STS(a+1) from hold (LDG'd one full iteration ago),
        // then issue LDG(a+2) -> has the whole next compute body to land
        if (a + 1 < NANG) sts12(&s_img[(a + 1) & 1][0], hold, rbase, zst);
        if (a + 2 < NANG) {
            y_n2 = yminf(a + 2);
            ldg12(hold, img_b + (size_t)(a + 2) * LL * LL, y_n2, rbase, zst);
        }
        y_c = y_n; y_n = y_n2;
    }

    // epilogue
    float inv1 = 1.0f / (n1 + 1e-11f);
    float inv2 = 1.0f / (n2 + 1e-11f);
    float *op = out + (((size_t)b * LL + px) * LL + py) * LL + z0;
    #pragma unroll
    for (int q = 0; q < 8; ++q) {
        float ax, ay, bx, by;
        unpack2(acc[2 * q],     ax, ay);
        unpack2(acc[2 * q + 1], bx, by);
        *reinterpret_cast<float4 *>(op + q * 4) =
            make_float4(ax * inv1, ay * inv1, bx * inv1, by * inv1);
    }
    float *op2 = op + LL;
    #pragma unroll
    for (int q = 0; q < 8; ++q) {
        float ax, ay, bx, by;
        unpack2(acc[16 + 2 * q],     ax, ay);
        unpack2(acc[16 + 2 * q + 1], bx, by);
        *reinterpret_cast<float4 *>(op2 + q * 4) =
            make_float4(ax * inv2, ay * inv2, bx * inv2, by * inv2);
    }
}

extern "C" void kernel_launch(void *const *d_in, const int *in_sizes, int n_in,
                              void *d_out, int out_size) {
    const float *image  = (const float *)d_in[0];
    const float *angles = (const float *)d_in[1];
    float *out = (float *)d_out;
    dim3 grid(128 /* 16 x-tiles * 8 y-tiles */, LL / ZC /*4*/, 2 /*B*/);
    bp_kernel<<<grid, TB>>>(image, angles, out);
}

// round 7
// speedup vs baseline: 1.1170x; 1.0261x over previous
#include <cuda_runtime.h>

#define LL    128
#define NANG  120
#define TB    128
#define TX    16
#define TY    16
#define ZC    16
#define ROWS  32
#define RS    20
#define NST   4       // staging loads per thread (ROWS*ZC/TB)

// ---- packed f32x2 helpers ----
__device__ __forceinline__ unsigned long long pack2(float x, float y) {
    unsigned long long r;
    asm("mov.b64 %0, {%1, %2};" : "=l"(r) : "f"(x), "f"(y));
    return r;
}
__device__ __forceinline__ void ffma2(unsigned long long &acc, unsigned long long v,
                                      unsigned long long w) {
    asm("fma.rn.f32x2 %0, %1, %2, %0;" : "+l"(acc) : "l"(v), "l"(w));
}
__device__ __forceinline__ void unpack2(unsigned long long v, float &x, float &y) {
    asm("mov.b64 {%0, %1}, %2;" : "=f"(x), "=f"(y) : "l"(v));
}
__device__ __forceinline__ void lds2(unsigned long long &a, unsigned long long &b,
                                     unsigned addr) {
    asm volatile("ld.shared.v2.u64 {%0, %1}, [%2];" : "=l"(a), "=l"(b) : "r"(addr));
}

__device__ __forceinline__ void ldg4(float r[NST], const float * __restrict__ img_a,
                                     int ymin, int rbase, int z) {
    #pragma unroll
    for (int k = 0; k < NST; ++k) {
        int gy = min(max(ymin + rbase + 8 * k, 0), LL - 1);
        r[k] = __ldg(img_a + gy * LL + z);
    }
}
__device__ __forceinline__ void sts4(float *dst, const float r[NST], int rbase, int z) {
    #pragma unroll
    for (int k = 0; k < NST; ++k) dst[(rbase + 8 * k) * RS + z] = r[k];
}

__global__ __launch_bounds__(TB, 7)
void bp_kernel(const float * __restrict__ image, const float * __restrict__ angles,
               float * __restrict__ out) {
    __shared__ float2 s_tab[NANG];
    __shared__ __align__(16) float s_img[2][ROWS * RS];

    const int tid = threadIdx.x;
    if (tid < NANG) {
        float ph = -angles[tid] * 0.017453292519943295f;
        float sv, cv;
        sincosf(ph, &sv, &cv);
        s_tab[tid] = make_float2(cv, sv);
    }

    const int tileX0 = (blockIdx.x & 7) * TX;
    const int tileY0 = (blockIdx.x >> 3) * TY;
    const int z0 = blockIdx.y * ZC;
    const int b  = blockIdx.z;

    const int warp = tid >> 5, lane = tid & 31;
    const int px = tileX0 + (warp & 1) * 8 + (lane & 7);
    const int pr = (warp >> 1) * 4 + (lane >> 3);      // pair index 0..7
    const int py = tileY0 + 2 * pr;
    const float Xp = px - 63.5f, Yp = py - 63.5f;
    const float X0f = tileX0 - 63.5f, X1f = X0f + (TX - 1);
    const float Y0f = tileY0 - 63.5f, Y1f = Y0f + (TY - 1);

    const float *img_b = image + (size_t)b * NANG * LL * LL + z0;
    const int zst = tid & 15, rbase = tid >> 4;

    unsigned long long acc[16];      // [0..7]=pixel1, [8..15]=pixel2
    #pragma unroll
    for (int i = 0; i < 16; ++i) acc[i] = 0ULL;
    float n1 = 0.0f, n2 = 0.0f;

    __syncthreads();  // s_tab ready

    const unsigned sm0 = (unsigned)__cvta_generic_to_shared(&s_img[0][0]);

    auto yminf = [&](int a) -> int {
        float2 cs = s_tab[a];
        float m = fminf(-cs.y * X0f, -cs.y * X1f) + fminf(cs.x * Y0f, cs.x * Y1f) + 63.5f;
        return (int)floorf(m) - 1;
    };

    // prologue: angle 0 staged into buf0; angle 1 LDG'd into hold regs
    int y_c = yminf(0);
    {
        float t[NST];
        ldg4(t, img_b, y_c, rbase, zst);
        sts4(&s_img[0][0], t, rbase, zst);
    }
    int y_n = yminf(1);
    float hold[NST];
    ldg4(hold, img_b + (size_t)LL * LL, y_n, rbase, zst);
    int y_n2 = y_n;

    for (int a = 0; a < NANG; ++a) {
        __syncthreads();   // buf[a&1] staged (STS drained); readers of buf[(a+1)&1] done

        const float2 cs = s_tab[a];
        const float c = cs.x, s = cs.y;

        float sx = fmaf(c, Xp, fmaf(s, Yp, 63.5f));
        float sy = fmaf(c, Yp, fmaf(-s, Xp, 63.5f));
        float sx2 = sx + s;
        float sy2 = sy + c;
        float y0f = floorf(sy), y2f = floorf(sy2);
        float wx  = sx  - floorf(sx);
        float wy  = sy  - y0f;
        float wx2 = sx2 - floorf(sx2);
        float wy2 = sy2 - y2f;

        float hx = 0.0f;
        if (sx >= 0.0f  && sx < 128.0f) hx = 1.0f - wx;
        if (sx >= -1.0f && sx < 127.0f) hx += wx;
        float A0 = (sy >= 0.0f  && sy < 128.0f) ? hx * (1.0f - wy) : 0.0f;
        float A1 = (sy >= -1.0f && sy < 127.0f) ? hx * wy          : 0.0f;

        float hx2 = 0.0f;
        if (sx2 >= 0.0f  && sx2 < 128.0f) hx2 = 1.0f - wx2;
        if (sx2 >= -1.0f && sx2 < 127.0f) hx2 += wx2;
        float B0 = (sy2 >= 0.0f  && sy2 < 128.0f) ? hx2 * (1.0f - wy2) : 0.0f;
        float B1 = (sy2 >= -1.0f && sy2 < 127.0f) ? hx2 * wy2          : 0.0f;

        n1 += A0 + A1;
        n2 += B0 + B1;

        bool dneg = (y2f < y0f), dpos = (y2f > y0f), dd = (y2f != y0f);
        int r0 = (int)fminf(y0f, y2f) - y_c;   // analytically in [0, ROWS-3]

        unsigned long long Wa0 = pack2(dneg ? 0.0f : A0, dneg ? 0.0f : A0);
        unsigned long long Wa1 = pack2(dneg ? A0 : A1,   dneg ? A0 : A1);
        unsigned long long Wa2 = pack2(dneg ? A1 : 0.0f, dneg ? A1 : 0.0f);
        unsigned long long Wb0 = pack2(dpos ? 0.0f : B0, dpos ? 0.0f : B0);
        unsigned long long Wb1 = pack2(dpos ? B0 : B1,   dpos ? B0 : B1);
        unsigned long long Wb2 = pack2(dpos ? B1 : 0.0f, dpos ? B1 : 0.0f);

        unsigned a0addr = sm0 + (unsigned)((a & 1) * (ROWS * RS * 4))
                              + (unsigned)r0 * (RS * 4);

        #pragma unroll
        for (int q = 0; q < 4; ++q) {
            unsigned long long p00, p01, p10, p11;
            unsigned long long p20 = 0ULL, p21 = 0ULL;
            lds2(p00, p01, a0addr + q * 16);
            lds2(p10, p11, a0addr + RS * 4 + q * 16);
            if (dd) lds2(p20, p21, a0addr + 2 * RS * 4 + q * 16);
            ffma2(acc[2 * q],     p00, Wa0);
            ffma2(acc[2 * q + 1], p01, Wa0);
            ffma2(acc[2 * q],     p10, Wa1);
            ffma2(acc[2 * q + 1], p11, Wa1);
            ffma2(acc[2 * q],     p20, Wa2);
            ffma2(acc[2 * q + 1], p21, Wa2);
            ffma2(acc[8 + 2 * q],     p00, Wb0);
            ffma2(acc[8 + 2 * q + 1], p01, Wb0);
            ffma2(acc[8 + 2 * q],     p10, Wb1);
            ffma2(acc[8 + 2 * q + 1], p11, Wb1);
            ffma2(acc[8 + 2 * q],     p20, Wb2);
            ffma2(acc[8 + 2 * q + 1], p21, Wb2);
        }

        // stage next: STS(a+1) from hold (LDG'd one full body ago),
        // then LDG(a+2) -> has the whole next compute body to land
        if (a + 1 < NANG) sts4(&s_img[(a + 1) & 1][0], hold, rbase, zst);
        if (a + 2 < NANG) {
            y_n2 = yminf(a + 2);
            ldg4(hold, img_b + (size_t)(a + 2) * LL * LL, y_n2, rbase, zst);
        }
        y_c = y_n; y_n = y_n2;
    }

    // epilogue
    float inv1 = 1.0f / (n1 + 1e-11f);
    float inv2 = 1.0f / (n2 + 1e-11f);
    float *op = out + (((size_t)b * LL + px) * LL + py) * LL + z0;
    #pragma unroll
    for (int q = 0; q < 4; ++q) {
        float ax, ay, bx, by;
        unpack2(acc[2 * q],     ax, ay);
        unpack2(acc[2 * q + 1], bx, by);
        *reinterpret_cast<float4 *>(op + q * 4) =
            make_float4(ax * inv1, ay * inv1, bx * inv1, by * inv1);
    }
    float *op2 = op + LL;
    #pragma unroll
    for (int q = 0; q < 4; ++q) {
        float ax, ay, bx, by;
        unpack2(acc[8 + 2 * q],     ax, ay);
        unpack2(acc[8 + 2 * q + 1], bx, by);
        *reinterpret_cast<float4 *>(op2 + q * 4) =
            make_float4(ax * inv2, ay * inv2, bx * inv2, by * inv2);
    }
}

extern "C" void kernel_launch(void *const *d_in, const int *in_sizes, int n_in,
                              void *d_out, int out_size) {
    const float *image  = (const float *)d_in[0];
    const float *angles = (const float *)d_in[1];
    float *out = (float *)d_out;
    dim3 grid(64, LL / ZC /*8*/, 2 /*B*/);
    bp_kernel<<<grid, TB>>>(image, angles, out);
}

// round 8
// speedup vs baseline: 1.1886x; 1.0641x over previous
#include <cuda_runtime.h>

#define LL    128
#define NANG  120
#define TB    128
#define TX    16
#define TY    16
#define ZC    16
#define ROWS  32
#define RS    20
#define NST   4

typedef unsigned long long u64t;

__device__ __forceinline__ u64t pack2(float x, float y) {
    u64t r;
    asm("mov.b64 %0, {%1, %2};" : "=l"(r) : "f"(x), "f"(y));
    return r;
}
__device__ __forceinline__ void ffma2(u64t &acc, u64t v, u64t w) {
    asm("fma.rn.f32x2 %0, %1, %2, %0;" : "+l"(acc) : "l"(v), "l"(w));
}
__device__ __forceinline__ void unpack2(u64t v, float &x, float &y) {
    asm("mov.b64 {%0, %1}, %2;" : "=f"(x), "=f"(y) : "l"(v));
}
__device__ __forceinline__ void lds2(u64t &a, u64t &b, unsigned addr) {
    asm volatile("ld.shared.v2.u64 {%0, %1}, [%2];" : "=l"(a), "=l"(b) : "r"(addr));
}

// edge/validity weight: sum of valid bilinear taps along one axis
__device__ __forceinline__ float gfun(float t) {
    return fmaxf(0.0f, fminf(fminf(t + 1.0f, 128.0f - t), 1.0f));
}

// zero-padded staging loads (OOB rows -> 0, so tap weights need no y-bounds tests)
__device__ __forceinline__ void ldg4z(float r[NST], const float * __restrict__ img_a,
                                      int ymin, int rbase, int z) {
    #pragma unroll
    for (int k = 0; k < NST; ++k) {
        int gy = ymin + rbase + 8 * k;
        r[k] = 0.0f;
        if ((unsigned)gy < (unsigned)LL) r[k] = __ldg(img_a + gy * LL + z);
    }
}
__device__ __forceinline__ void sts4(float *dst, const float r[NST], int rbase, int z) {
    #pragma unroll
    for (int k = 0; k < NST; ++k) dst[(rbase + 8 * k) * RS + z] = r[k];
}

// inner core: pixel P uses rows 0,1 (weights Wp0,Wp1); pixel Q uses rows 0,1,2
__device__ __forceinline__ void inner3(unsigned addr,
                                       u64t Wp0, u64t Wp1,
                                       u64t Wq0, u64t Wq1, u64t Wq2,
                                       u64t *accP, u64t *accQ) {
    #pragma unroll
    for (int q = 0; q < 4; ++q) {
        u64t p00, p01, p10, p11, p20, p21;
        lds2(p00, p01, addr + q * 16);
        lds2(p10, p11, addr + RS * 4 + q * 16);
        lds2(p20, p21, addr + 2 * RS * 4 + q * 16);
        ffma2(accP[2 * q],     p00, Wp0);
        ffma2(accP[2 * q + 1], p01, Wp0);
        ffma2(accP[2 * q],     p10, Wp1);
        ffma2(accP[2 * q + 1], p11, Wp1);
        ffma2(accQ[2 * q],     p00, Wq0);
        ffma2(accQ[2 * q + 1], p01, Wq0);
        ffma2(accQ[2 * q],     p10, Wq1);
        ffma2(accQ[2 * q + 1], p11, Wq1);
        ffma2(accQ[2 * q],     p20, Wq2);
        ffma2(accQ[2 * q + 1], p21, Wq2);
    }
}

__global__ __launch_bounds__(TB, 7)
void bp_kernel(const float * __restrict__ image, const float * __restrict__ angles,
               float * __restrict__ out) {
    __shared__ float4 s_tab[NANG];     // (cos, sin, unused, ymin-as-int-bits)
    __shared__ __align__(16) float s_img[2][ROWS * RS];

    const int tid = threadIdx.x;
    const int tileX0 = (blockIdx.x & 7) * TX;
    const int tileY0 = (blockIdx.x >> 3) * TY;
    const float X0f = tileX0 - 63.5f, X1f = X0f + (TX - 1);
    const float Y0f = tileY0 - 63.5f, Y1f = Y0f + (TY - 1);

    if (tid < NANG) {
        float ph = -angles[tid] * 0.017453292519943295f;
        float sv, cv;
        sincosf(ph, &sv, &cv);
        float m = fminf(-sv * X0f, -sv * X1f) + fminf(cv * Y0f, cv * Y1f) + 63.5f;
        int ym = (int)floorf(m) - 1;
        s_tab[tid] = make_float4(cv, sv, 0.0f, __int_as_float(ym));
    }

    const int z0 = blockIdx.y * ZC;
    const int b  = blockIdx.z;

    const int warp = tid >> 5, lane = tid & 31;
    const int px = tileX0 + (warp & 1) * 8 + (lane & 7);
    const int pr = (warp >> 1) * 4 + (lane >> 3);
    const int py = tileY0 + 2 * pr;
    const float Xp = px - 63.5f, Yp = py - 63.5f;

    const float *img_b = image + (size_t)b * NANG * LL * LL + z0;
    const int zst = tid & 15, rbase = tid >> 4;

    u64t acc[16];    // [0..7]=pixel1(py), [8..15]=pixel2(py+1)
    #pragma unroll
    for (int i = 0; i < 16; ++i) acc[i] = 0ULL;
    float n1 = 0.0f, n2 = 0.0f;

    __syncthreads();  // s_tab ready

    const unsigned sm0 = (unsigned)__cvta_generic_to_shared(&s_img[0][0]);

    // prologue: angle 0 staged into buf0; angle 1 LDG'd into hold regs
    {
        float t[NST];
        ldg4z(t, img_b, __float_as_int(s_tab[0].w), rbase, zst);
        sts4(&s_img[0][0], t, rbase, zst);
    }
    float hold[NST];
    ldg4z(hold, img_b + (size_t)LL * LL, __float_as_int(s_tab[1].w), rbase, zst);

    for (int a = 0; a < NANG; ++a) {
        __syncthreads();   // buf[a&1] staged; readers of buf[(a+1)&1] done

        const float4 tb = s_tab[a];
        const float c = tb.x, s = tb.y;
        const int   ya = __float_as_int(tb.w);

        float sx = fmaf(c, Xp, fmaf(s, Yp, 63.5f));
        float sy = fmaf(c, Yp, fmaf(-s, Xp, 63.5f));
        float sx2 = sx + s;
        float sy2 = sy + c;
        float y0f = floorf(sy), y2f = floorf(sy2);
        float wy  = sy  - y0f;
        float wy2 = sy2 - y2f;

        float hx  = gfun(sx);
        float hx2 = gfun(sx2);
        n1 = fmaf(hx,  gfun(sy),  n1);
        n2 = fmaf(hx2, gfun(sy2), n2);

        float A1 = hx  * wy,  A0 = hx  - A1;   // taps rows y0, y0+1 (OOB data = 0)
        float B1 = hx2 * wy2, B0 = hx2 - B1;

        const unsigned smb = sm0 + (unsigned)((a & 1) * (ROWS * RS * 4));

        if (c >= 0.0f) {
            // y2f >= y0f: pixel1 at window rows 0,1; pixel2 shifted by dd
            bool dd = (y2f > y0f);
            int r0 = (int)y0f - ya;                 // in [0, ROWS-3]
            float q0 = dd ? 0.0f : B0;
            float q1 = dd ? B0   : B1;
            float q2 = dd ? B1   : 0.0f;
            inner3(smb + (unsigned)r0 * (RS * 4),
                   pack2(A0, A0), pack2(A1, A1),
                   pack2(q0, q0), pack2(q1, q1), pack2(q2, q2),
                   acc, acc + 8);
        } else {
            // y2f <= y0f: pixel2 at window rows 0,1; pixel1 shifted by dd
            bool dd = (y2f < y0f);
            int r0 = (int)y2f - ya;
            float q0 = dd ? 0.0f : A0;
            float q1 = dd ? A0   : A1;
            float q2 = dd ? A1   : 0.0f;
            inner3(smb + (unsigned)r0 * (RS * 4),
                   pack2(B0, B0), pack2(B1, B1),
                   pack2(q0, q0), pack2(q1, q1), pack2(q2, q2),
                   acc + 8, acc);
        }

        // stage next: STS(a+1) from hold (LDG'd one full body ago), then LDG(a+2)
        if (a + 1 < NANG) sts4(&s_img[(a + 1) & 1][0], hold, rbase, zst);
        if (a + 2 < NANG) {
            ldg4z(hold, img_b + (size_t)(a + 2) * LL * LL,
                  __float_as_int(s_tab[a + 2].w), rbase, zst);
        }
    }

    // epilogue: out = obj / (norm + delta)
    float inv1 = 1.0f / (n1 + 1e-11f);
    float inv2 = 1.0f / (n2 + 1e-11f);
    float *op = out + (((size_t)b * LL + px) * LL + py) * LL + z0;
    #pragma unroll
    for (int q = 0; q < 4; ++q) {
        float ax, ay, bx, by;
        unpack2(acc[2 * q],     ax, ay);
        unpack2(acc[2 * q + 1], bx, by);
        *reinterpret_cast<float4 *>(op + q * 4) =
            make_float4(ax * inv1, ay * inv1, bx * inv1, by * inv1);
    }
    float *op2 = op + LL;
    #pragma unroll
    for (int q = 0; q < 4; ++q) {
        float ax, ay, bx, by;
        unpack2(acc[8 + 2 * q],     ax, ay);
        unpack2(acc[8 + 2 * q + 1], bx, by);
        *reinterpret_cast<float4 *>(op2 + q * 4) =
            make_float4(ax * inv2, ay * inv2, bx * inv2, by * inv2);
    }
}

extern "C" void kernel_launch(void *const *d_in, const int *in_sizes, int n_in,
                              void *d_out, int out_size) {
    const float *image  = (const float *)d_in[0];
    const float *angles = (const float *)d_in[1];
    float *out = (float *)d_out;
    dim3 grid(64, LL / ZC /*8*/, 2 /*B*/);
    bp_kernel<<<grid, TB>>>(image, angles, out);
}